// round 16
// baseline (speedup 1.0000x reference)
#include <cuda_runtime.h>
#include <cstdint>

// ResidualGraphConv via Horner over combined channels Wc[d] = [W1[d]; W2[d]]:
//   V = U3;  V = V*A + U2;  V = V*A + U1;  out = V*A + U0 (+bias, relu upper 32)
// with U_d = Wc[d] @ x fused as two trailing K=32 chunks of each GEMM.
//
// mma.sync.m16n8k8 tf32. V is tf32-RNA-rounded at the producer epilogue, so
// the A operand needs NO cvt in the main loop; adj/x/W cvt.rna'd at fragment
// load. cp.async 3-stage pipeline. CTA tile 64x64, 256 threads (8 warps),
// warp tile 32x16 -> 27.7 warps/SM supplied (vs 13.8 in the 128-thr version),
// single wave: grid 512 <= 4 CTAs/SM * 148.

#define BATCH 16
#define CCH   64
#define NN    2048
#define NT    64
#define KB    32
#define LDA   36                        // 32 data + 4 pad floats
#define LDB   72                        // 64 data + 8 pad floats
#define A_FL  (CCH * LDA)               // 2304 floats
#define B_FL  (KB * LDB)                // 2304 floats
#define STAGE_FL (A_FL + B_FL)          // 4608 floats = 18432 B
#define STAGES 3
#define SMEM_BYTES (STAGES * STAGE_FL * 4)   // 55296 B

__device__ float g_V0[BATCH * CCH * NN];
__device__ float g_V1[BATCH * CCH * NN];

__device__ __forceinline__ uint32_t ftf32(float v) {
    uint32_t u;
    asm("cvt.rna.tf32.f32 %0, %1;" : "=r"(u) : "f"(v));
    return u;
}
__device__ __forceinline__ float ftf32f(float v) { return __uint_as_float(ftf32(v)); }

__device__ __forceinline__ void cp_async16(uint32_t smem_addr, const float* gptr) {
    asm volatile("cp.async.cg.shared.global [%0], [%1], 16;\n"
                 :: "r"(smem_addr), "l"(gptr));
}
__device__ __forceinline__ void cp_commit() {
    asm volatile("cp.async.commit_group;\n" ::: "memory");
}
__device__ __forceinline__ void cp_wait1() {
    asm volatile("cp.async.wait_group 1;\n" ::: "memory");
}

__device__ __forceinline__ void mma_tf32(float* c, const uint32_t* a, const uint32_t* bb) {
    asm volatile(
        "mma.sync.aligned.m16n8k8.row.col.f32.tf32.tf32.f32 "
        "{%0,%1,%2,%3}, {%4,%5,%6,%7}, {%8,%9}, {%0,%1,%2,%3};\n"
        : "+f"(c[0]), "+f"(c[1]), "+f"(c[2]), "+f"(c[3])
        : "r"(a[0]), "r"(a[1]), "r"(a[2]), "r"(a[3]), "r"(bb[0]), "r"(bb[1]));
}

// vin_sel: 0 -> g_V0, 1 -> g_V1. vout_sel: 0 -> g_V0 (tf32-rounded),
// 1 -> g_V1 (tf32-rounded), 2 -> dout (full f32, +bias, relu upper half)
__global__ void __launch_bounds__(256, 4)
horner_kernel(const float* __restrict__ adj,
              const float* __restrict__ x,
              const float* __restrict__ W1,
              const float* __restrict__ W2,
              const float* __restrict__ bias1,
              const float* __restrict__ bias2,
              float* __restrict__ dout,
              int nk_main, int deg, int vin_sel, int vout_sel) {
    extern __shared__ float sm[];

    const int tid  = threadIdx.x;          // 0..255
    const int lane = tid & 31;
    const int wid  = tid >> 5;             // 0..7
    const int wm   = wid & 1;              // m-half: rows wm*32..+31
    const int wn   = wid >> 1;             // n-strip: cols wn*16..+15
    const int g    = lane >> 2;            // 0..7
    const int t    = lane & 3;             // 0..3
    const int b    = blockIdx.y;
    const int m0   = blockIdx.x * NT;

    const float* Vin  = vin_sel ? g_V1 : g_V0;
    float*       Vout = (vout_sel == 0) ? g_V0 : ((vout_sel == 1) ? g_V1 : dout);

    const int nchunks = nk_main + 2;

    const uint32_t smbase = (uint32_t)__cvta_generic_to_shared(sm);

    // ---- staging: 4 cp.async.16 per thread per chunk, fully coalesced ----
    auto load_chunk = [&](int cc, int stage) {
        if (cc < nchunks) {
            const bool isU = (cc >= nk_main);
            const int  k0  = cc * KB;
            const int  ci0 = (cc - nk_main) * KB;
            const uint32_t sA = smbase + (uint32_t)(stage * STAGE_FL) * 4u;
            const uint32_t sB = sA + (uint32_t)A_FL * 4u;
            // A: 64 rows x 32 floats = 512 float4 slots, 2 iters of 256 threads
#pragma unroll
            for (int i = 0; i < 2; i++) {
                const int li  = i * 256 + tid;
                const int row = li >> 3;
                const int q   = li & 7;
                const float* src;
                if (!isU) {
                    src = Vin + ((b << 6) + row) * NN + k0 + (q << 2);
                } else {
                    const float* W = (row < 32) ? W1 : W2;
                    src = W + ((deg * 32 + (row & 31)) << 6) + ci0 + (q << 2);
                }
                cp_async16(sA + (uint32_t)(row * LDA + (q << 2)) * 4u, src);
            }
            // B: 32 k-rows x 64 floats = 512 float4 slots
#pragma unroll
            for (int i = 0; i < 2; i++) {
                const int li = i * 256 + tid;
                const int kr = li >> 4;
                const int q  = li & 15;
                const float* src;
                if (!isU) {
                    src = adj + (size_t)(b * NN + k0 + kr) * NN + m0 + (q << 2);
                } else {
                    src = x + ((b << 6) + ci0 + kr) * NN + m0 + (q << 2);
                }
                cp_async16(sB + (uint32_t)(kr * LDB + (q << 2)) * 4u, src);
            }
        }
        cp_commit();   // always commit to keep group counting uniform
    };

    float acc[2][2][4];
#pragma unroll
    for (int mt = 0; mt < 2; mt++)
#pragma unroll
        for (int jn = 0; jn < 2; jn++)
#pragma unroll
            for (int q = 0; q < 4; q++) acc[mt][jn][q] = 0.0f;

    // ---- prologue ----
    load_chunk(0, 0);
    load_chunk(1, 1);

    for (int cc = 0; cc < nchunks; cc++) {
        cp_wait1();            // chunk cc landed (cc+1 may still be in flight)
        __syncthreads();       // visibility + all warps done with stage (cc-1)%3

        load_chunk(cc + 2, (cc + 2) % STAGES);

        const float* S  = sm + (cc % STAGES) * STAGE_FL;
        const float* SB = S + A_FL;
        const bool   isU = (cc >= nk_main);   // uniform per chunk

#pragma unroll
        for (int kk = 0; kk < 4; kk++) {
            const int kb = kk * 8;
            uint32_t a[2][4];
#pragma unroll
            for (int mt = 0; mt < 2; mt++) {
                const int base = (wm * 32 + mt * 16 + g) * LDA + kb + t;
                float v0 = S[base];
                float v1 = S[base + 8 * LDA];
                float v2 = S[base + 4];
                float v3 = S[base + 8 * LDA + 4];
                if (isU) {   // W needs RNA rounding; V is pre-rounded (identity)
                    a[mt][0] = ftf32(v0); a[mt][1] = ftf32(v1);
                    a[mt][2] = ftf32(v2); a[mt][3] = ftf32(v3);
                } else {
                    a[mt][0] = __float_as_uint(v0); a[mt][1] = __float_as_uint(v1);
                    a[mt][2] = __float_as_uint(v2); a[mt][3] = __float_as_uint(v3);
                }
            }
#pragma unroll
            for (int jn = 0; jn < 2; jn++) {
                const int col = wn * 16 + jn * 8 + g;
                uint32_t bf[2];
                bf[0] = ftf32(SB[(kb + t) * LDB + col]);
                bf[1] = ftf32(SB[(kb + t + 4) * LDB + col]);
                mma_tf32(acc[0][jn], a[0], bf);
                mma_tf32(acc[1][jn], a[1], bf);
            }
        }
    }

    // ---- epilogue ----
#pragma unroll
    for (int mt = 0; mt < 2; mt++) {
        const int r0 = wm * 32 + mt * 16 + g;
        const int r1 = r0 + 8;
        float add0 = 0.0f, add1 = 0.0f;
        bool relu = false;
        if (vout_sel == 2) {
            add0 = (r0 < 32) ? bias1[r0] : bias2[r0 - 32];
            add1 = (r1 < 32) ? bias1[r1] : bias2[r1 - 32];
            relu = (wm == 1);   // rows 32..63 = nonlinear half
        }
#pragma unroll
        for (int jn = 0; jn < 2; jn++) {
            const int m = m0 + wn * 16 + jn * 8 + 2 * t;
            float v0 = acc[mt][jn][0], v1 = acc[mt][jn][1];   // row r0
            float v2 = acc[mt][jn][2], v3 = acc[mt][jn][3];   // row r1
            if (vout_sel == 2) {
                v0 += add0; v1 += add0;
                v2 += add1; v3 += add1;
                if (relu) {
                    v0 = fmaxf(v0, 0.0f); v1 = fmaxf(v1, 0.0f);
                    v2 = fmaxf(v2, 0.0f); v3 = fmaxf(v3, 0.0f);
                }
            } else {
                // producer-side tf32 rounding (bit-identical to consumer-side)
                v0 = ftf32f(v0); v1 = ftf32f(v1);
                v2 = ftf32f(v2); v3 = ftf32f(v3);
            }
            *reinterpret_cast<float2*>(&Vout[((b << 6) + r0) * NN + m]) = make_float2(v0, v1);
            *reinterpret_cast<float2*>(&Vout[((b << 6) + r1) * NN + m]) = make_float2(v2, v3);
        }
    }
}

extern "C" void kernel_launch(void* const* d_in, const int* in_sizes, int n_in,
                              void* d_out, int out_size) {
    (void)in_sizes; (void)n_in; (void)out_size;
    const float* adj = (const float*)d_in[0];   // [16,2048,2048]
    const float* x   = (const float*)d_in[1];   // [16,64,2048]
    const float* W1  = (const float*)d_in[2];   // [4,32,64]
    const float* b1  = (const float*)d_in[3];   // [32]
    const float* W2  = (const float*)d_in[4];   // [4,32,64]
    const float* b2  = (const float*)d_in[5];   // [32]
    float* out = (float*)d_out;                 // [16,64,2048]

    static bool attr_set = false;
    if (!attr_set) {
        cudaFuncSetAttribute(horner_kernel,
                             cudaFuncAttributeMaxDynamicSharedMemorySize, SMEM_BYTES);
        attr_set = true;
    }

    dim3 grid(NN / NT, BATCH);   // 32 x 16 = 512 CTAs -> single wave @ 4 CTA/SM
    dim3 block(256);

    // V0 = U3 (projection only)
    horner_kernel<<<grid, block, SMEM_BYTES>>>(adj, x, W1, W2, b1, b2, out, 0, 3, 0, 0);
    // V1 = V0*A + U2
    horner_kernel<<<grid, block, SMEM_BYTES>>>(adj, x, W1, W2, b1, b2, out, NN / KB, 2, 0, 1);
    // V0 = V1*A + U1
    horner_kernel<<<grid, block, SMEM_BYTES>>>(adj, x, W1, W2, b1, b2, out, NN / KB, 1, 1, 0);
    // out = V0*A + U0 + bias, relu upper half
    horner_kernel<<<grid, block, SMEM_BYTES>>>(adj, x, W1, W2, b1, b2, out, NN / KB, 0, 0, 2);
}

// round 17
// speedup vs baseline: 1.2932x; 1.2932x over previous
#include <cuda_runtime.h>
#include <cstdint>

// ResidualGraphConv via Horner over combined channels Wc[d] = [W1[d]; W2[d]]:
//   V = U3;  V = V*A + U2;  V = V*A + U1;  out = V*A + U0 (+bias, relu upper 32)
// with U_d = Wc[d] @ x fused as two trailing K=32 chunks of each GEMM.
//
// mma.sync.m16n8k8 tf32. V is tf32-RNA-rounded at the producer epilogue, so
// the A operand needs NO cvt on main chunks; adj/x/W cvt.rna'd at fragment
// load. cp.async 3-stage pipeline. CTA tile 64x64, 128 threads, warp tile
// 32x32 (R15 config — best measured). NEW: explicit register double-buffering
// of fragments across kk-steps + isU branch hoisted out of the hot loop, to
// hide the LDS->CVT->MMA dependency chain that bound R15 at issue=52%.

#define BATCH 16
#define CCH   64
#define NN    2048
#define NT    64
#define KB    32
#define LDA   36                        // 32 data + 4 pad floats
#define LDB   72                        // 64 data + 8 pad floats
#define A_FL  (CCH * LDA)               // 2304 floats
#define B_FL  (KB * LDB)                // 2304 floats
#define STAGE_FL (A_FL + B_FL)          // 4608 floats = 18432 B
#define STAGES 3
#define SMEM_BYTES (STAGES * STAGE_FL * 4)   // 55296 B

__device__ float g_V0[BATCH * CCH * NN];
__device__ float g_V1[BATCH * CCH * NN];

__device__ __forceinline__ uint32_t ftf32(float v) {
    uint32_t u;
    asm("cvt.rna.tf32.f32 %0, %1;" : "=r"(u) : "f"(v));
    return u;
}
__device__ __forceinline__ float ftf32f(float v) { return __uint_as_float(ftf32(v)); }

__device__ __forceinline__ void cp_async16(uint32_t smem_addr, const float* gptr) {
    asm volatile("cp.async.cg.shared.global [%0], [%1], 16;\n"
                 :: "r"(smem_addr), "l"(gptr));
}
__device__ __forceinline__ void cp_commit() {
    asm volatile("cp.async.commit_group;\n" ::: "memory");
}
__device__ __forceinline__ void cp_wait1() {
    asm volatile("cp.async.wait_group 1;\n" ::: "memory");
}

__device__ __forceinline__ void mma_tf32(float* c, const uint32_t* a, const uint32_t* bb) {
    asm volatile(
        "mma.sync.aligned.m16n8k8.row.col.f32.tf32.tf32.f32 "
        "{%0,%1,%2,%3}, {%4,%5,%6,%7}, {%8,%9}, {%0,%1,%2,%3};\n"
        : "+f"(c[0]), "+f"(c[1]), "+f"(c[2]), "+f"(c[3])
        : "r"(a[0]), "r"(a[1]), "r"(a[2]), "r"(a[3]), "r"(bb[0]), "r"(bb[1]));
}

// vin_sel: 0 -> g_V0, 1 -> g_V1. vout_sel: 0 -> g_V0 (tf32-rounded),
// 1 -> g_V1 (tf32-rounded), 2 -> dout (full f32, +bias, relu upper half)
__global__ void __launch_bounds__(128, 4)
horner_kernel(const float* __restrict__ adj,
              const float* __restrict__ x,
              const float* __restrict__ W1,
              const float* __restrict__ W2,
              const float* __restrict__ bias1,
              const float* __restrict__ bias2,
              float* __restrict__ dout,
              int nk_main, int deg, int vin_sel, int vout_sel) {
    extern __shared__ float sm[];

    const int tid  = threadIdx.x;          // 0..127
    const int lane = tid & 31;
    const int wid  = tid >> 5;             // 0..3
    const int wm   = wid & 1;              // m-half: rows wm*32..+31
    const int wn   = wid >> 1;             // n-half: cols wn*32..+31
    const int g    = lane >> 2;            // 0..7
    const int t    = lane & 3;             // 0..3
    const int b    = blockIdx.y;
    const int m0   = blockIdx.x * NT;

    const float* Vin  = vin_sel ? g_V1 : g_V0;
    float*       Vout = (vout_sel == 0) ? g_V0 : ((vout_sel == 1) ? g_V1 : dout);

    const int nchunks = nk_main + 2;

    const uint32_t smbase = (uint32_t)__cvta_generic_to_shared(sm);

    // ---- staging: 8 cp.async.16 per thread per chunk, fully coalesced ----
    auto load_chunk = [&](int cc, int stage) {
        if (cc < nchunks) {
            const bool isU = (cc >= nk_main);
            const int  k0  = cc * KB;
            const int  ci0 = (cc - nk_main) * KB;
            const uint32_t sA = smbase + (uint32_t)(stage * STAGE_FL) * 4u;
            const uint32_t sB = sA + (uint32_t)A_FL * 4u;
            // A: 64 rows x 32 floats = 512 float4 slots
#pragma unroll
            for (int i = 0; i < 4; i++) {
                const int li  = i * 128 + tid;
                const int row = li >> 3;
                const int q   = li & 7;
                const float* src;
                if (!isU) {
                    src = Vin + ((b << 6) + row) * NN + k0 + (q << 2);
                } else {
                    const float* W = (row < 32) ? W1 : W2;
                    src = W + ((deg * 32 + (row & 31)) << 6) + ci0 + (q << 2);
                }
                cp_async16(sA + (uint32_t)(row * LDA + (q << 2)) * 4u, src);
            }
            // B: 32 k-rows x 64 floats = 512 float4 slots
#pragma unroll
            for (int i = 0; i < 4; i++) {
                const int li = i * 128 + tid;
                const int kr = li >> 4;
                const int q  = li & 15;
                const float* src;
                if (!isU) {
                    src = adj + (size_t)(b * NN + k0 + kr) * NN + m0 + (q << 2);
                } else {
                    src = x + ((b << 6) + ci0 + kr) * NN + m0 + (q << 2);
                }
                cp_async16(sB + (uint32_t)(kr * LDB + (q << 2)) * 4u, src);
            }
        }
        cp_commit();   // always commit to keep group counting uniform
    };

    float acc[2][4][4];
#pragma unroll
    for (int mt = 0; mt < 2; mt++)
#pragma unroll
        for (int jn = 0; jn < 4; jn++)
#pragma unroll
            for (int q = 0; q < 4; q++) acc[mt][jn][q] = 0.0f;

    // ---- prologue ----
    load_chunk(0, 0);
    load_chunk(1, 1);

    // fragment double buffers
    uint32_t aR[2][2][4];   // [buf][mt][elem]
    uint32_t bR[2][4][2];   // [buf][jn][elem]

    for (int cc = 0; cc < nchunks; cc++) {
        cp_wait1();            // chunk cc landed (cc+1 may still be in flight)
        __syncthreads();       // visibility + all warps done with stage (cc-1)%3

        load_chunk(cc + 2, (cc + 2) % STAGES);

        const float* S  = sm + (cc % STAGES) * STAGE_FL;
        const float* SB = S + A_FL;
        const bool   isU = (cc >= nk_main);   // uniform per chunk

        // fragment loaders (kk -> buf)
        auto ldA_main = [&](int kk, int buf) {
            const int kb = kk * 8;
#pragma unroll
            for (int mt = 0; mt < 2; mt++) {
                const int base = (wm * 32 + mt * 16 + g) * LDA + kb + t;
                aR[buf][mt][0] = __float_as_uint(S[base]);
                aR[buf][mt][1] = __float_as_uint(S[base + 8 * LDA]);
                aR[buf][mt][2] = __float_as_uint(S[base + 4]);
                aR[buf][mt][3] = __float_as_uint(S[base + 8 * LDA + 4]);
            }
        };
        auto ldA_u = [&](int kk, int buf) {
            const int kb = kk * 8;
#pragma unroll
            for (int mt = 0; mt < 2; mt++) {
                const int base = (wm * 32 + mt * 16 + g) * LDA + kb + t;
                aR[buf][mt][0] = ftf32(S[base]);
                aR[buf][mt][1] = ftf32(S[base + 8 * LDA]);
                aR[buf][mt][2] = ftf32(S[base + 4]);
                aR[buf][mt][3] = ftf32(S[base + 8 * LDA + 4]);
            }
        };
        auto ldB = [&](int kk, int buf) {
            const int kb = kk * 8;
#pragma unroll
            for (int jn = 0; jn < 4; jn++) {
                const int col = wn * 32 + jn * 8 + g;
                bR[buf][jn][0] = ftf32(SB[(kb + t) * LDB + col]);
                bR[buf][jn][1] = ftf32(SB[(kb + t + 4) * LDB + col]);
            }
        };
        auto mma_kk = [&](int buf) {
#pragma unroll
            for (int jn = 0; jn < 4; jn++) {
                mma_tf32(acc[0][jn], aR[buf][0], bR[buf][jn]);
                mma_tf32(acc[1][jn], aR[buf][1], bR[buf][jn]);
            }
        };

        if (!isU) {   // main chunks: A is pre-rounded tf32, no cvt
            ldA_main(0, 0); ldB(0, 0);
#pragma unroll
            for (int kk = 0; kk < 4; kk++) {
                const int cur = kk & 1, nxt = cur ^ 1;
                if (kk < 3) { ldA_main(kk + 1, nxt); ldB(kk + 1, nxt); }
                mma_kk(cur);
            }
        } else {      // W chunks (2 per step): cvt A too
            ldA_u(0, 0); ldB(0, 0);
#pragma unroll
            for (int kk = 0; kk < 4; kk++) {
                const int cur = kk & 1, nxt = cur ^ 1;
                if (kk < 3) { ldA_u(kk + 1, nxt); ldB(kk + 1, nxt); }
                mma_kk(cur);
            }
        }
    }

    // ---- epilogue ----
#pragma unroll
    for (int mt = 0; mt < 2; mt++) {
        const int r0 = wm * 32 + mt * 16 + g;
        const int r1 = r0 + 8;
        float add0 = 0.0f, add1 = 0.0f;
        bool relu = false;
        if (vout_sel == 2) {
            add0 = (r0 < 32) ? bias1[r0] : bias2[r0 - 32];
            add1 = (r1 < 32) ? bias1[r1] : bias2[r1 - 32];
            relu = (wm == 1);   // rows 32..63 = nonlinear half
        }
#pragma unroll
        for (int jn = 0; jn < 4; jn++) {
            const int m = m0 + wn * 32 + jn * 8 + 2 * t;
            float v0 = acc[mt][jn][0], v1 = acc[mt][jn][1];   // row r0
            float v2 = acc[mt][jn][2], v3 = acc[mt][jn][3];   // row r1
            if (vout_sel == 2) {
                v0 += add0; v1 += add0;
                v2 += add1; v3 += add1;
                if (relu) {
                    v0 = fmaxf(v0, 0.0f); v1 = fmaxf(v1, 0.0f);
                    v2 = fmaxf(v2, 0.0f); v3 = fmaxf(v3, 0.0f);
                }
            } else {
                // producer-side tf32 rounding (bit-identical to consumer-side)
                v0 = ftf32f(v0); v1 = ftf32f(v1);
                v2 = ftf32f(v2); v3 = ftf32f(v3);
            }
            *reinterpret_cast<float2*>(&Vout[((b << 6) + r0) * NN + m]) = make_float2(v0, v1);
            *reinterpret_cast<float2*>(&Vout[((b << 6) + r1) * NN + m]) = make_float2(v2, v3);
        }
    }
}

extern "C" void kernel_launch(void* const* d_in, const int* in_sizes, int n_in,
                              void* d_out, int out_size) {
    (void)in_sizes; (void)n_in; (void)out_size;
    const float* adj = (const float*)d_in[0];   // [16,2048,2048]
    const float* x   = (const float*)d_in[1];   // [16,64,2048]
    const float* W1  = (const float*)d_in[2];   // [4,32,64]
    const float* b1  = (const float*)d_in[3];   // [32]
    const float* W2  = (const float*)d_in[4];   // [4,32,64]
    const float* b2  = (const float*)d_in[5];   // [32]
    float* out = (float*)d_out;                 // [16,64,2048]

    static bool attr_set = false;
    if (!attr_set) {
        cudaFuncSetAttribute(horner_kernel,
                             cudaFuncAttributeMaxDynamicSharedMemorySize, SMEM_BYTES);
        attr_set = true;
    }

    dim3 grid(NN / NT, BATCH);   // 32 x 16 = 512 CTAs
    dim3 block(128);

    // V0 = U3 (projection only)
    horner_kernel<<<grid, block, SMEM_BYTES>>>(adj, x, W1, W2, b1, b2, out, 0, 3, 0, 0);
    // V1 = V0*A + U2
    horner_kernel<<<grid, block, SMEM_BYTES>>>(adj, x, W1, W2, b1, b2, out, NN / KB, 2, 0, 1);
    // V0 = V1*A + U1
    horner_kernel<<<grid, block, SMEM_BYTES>>>(adj, x, W1, W2, b1, b2, out, NN / KB, 1, 1, 0);
    // out = V0*A + U0 + bias, relu upper half
    horner_kernel<<<grid, block, SMEM_BYTES>>>(adj, x, W1, W2, b1, b2, out, NN / KB, 0, 0, 2);
}